// round 14
// baseline (speedup 1.0000x reference)
#include <cuda_runtime.h>
#include <cuda_fp16.h>
#include <cstdint>

// ---------------- problem constants ----------------
#define BB 4
#define LL 1024
#define DD 768
#define HH 12
#define NEE 42
#define MM 8
#define ST (NEE*NEE)     // 1764
#define NPAIR 903        // pairs with s<=t
#define PACK 1024        // padded packed rows (8 x 128)

// ---------------- device scratch ----------------
__device__ __half g_Wh[(size_t)BB*PACK*LL];   // packed symmetric W (fp16)
__device__ __half g_BT[(size_t)BB*DD*LL];     // seq^T (fp16) [b][d][l]
__device__ float  g_Zp[BB*32*PACK];           // per-ltile partial row sums
__device__ int    g_ps[PACK];                 // packed row -> s
__device__ int    g_pt[PACK];                 // packed row -> t
__device__ int    g_cnt[BB];                  // per-batch prep-done counters

// ---------------- PTX helpers ----------------
__device__ __forceinline__ uint32_t smem_u32(const void* p) {
    uint32_t a;
    asm("{ .reg .u64 t; cvta.to.shared.u64 t, %1; cvt.u32.u64 %0, t; }" : "=r"(a) : "l"(p));
    return a;
}
__device__ __forceinline__ void cp16(uint32_t dst, const void* src) {
    asm volatile("cp.async.cg.shared.global [%0], [%1], 16;" :: "r"(dst), "l"(src));
}
#define CP_COMMIT() asm volatile("cp.async.commit_group;" ::: "memory")
#define CP_WAIT2()  asm volatile("cp.async.wait_group 2;" ::: "memory")
#define CP_WAIT0()  asm volatile("cp.async.wait_group 0;" ::: "memory")

__device__ __forceinline__ void ldsm4(uint32_t& r0, uint32_t& r1, uint32_t& r2, uint32_t& r3,
                                      uint32_t addr) {
    asm volatile("ldmatrix.sync.aligned.m8n8.x4.shared.b16 {%0,%1,%2,%3}, [%4];"
                 : "=r"(r0), "=r"(r1), "=r"(r2), "=r"(r3) : "r"(addr));
}
__device__ __forceinline__ void mma16816(float* d, const uint32_t* a, const uint32_t* b) {
    asm volatile(
        "mma.sync.aligned.m16n8k16.row.col.f32.f16.f16.f32 "
        "{%0,%1,%2,%3},{%4,%5,%6,%7},{%8,%9},{%0,%1,%2,%3};"
        : "+f"(d[0]), "+f"(d[1]), "+f"(d[2]), "+f"(d[3])
        : "r"(a[0]), "r"(a[1]), "r"(a[2]), "r"(a[3]), "r"(b[0]), "r"(b[1]));
}

// ---------------- Kernel R: reset flags ----------------
__global__ void reset_flags() {
    if (threadIdx.x < BB) g_cnt[threadIdx.x] = 0;
}

// ---------------- Kernel P: merged prep [R8 compute, + done-flags] ----------------
// blocks 0..127   : fused ent_att + Gram + fp16 W + Z partials
// blocks 128..511 : seq transpose+convert -> g_BT
// 1024 threads, dyn smem 64512 B
__global__ void __launch_bounds__(1024) prep_kernel(const float* __restrict__ seq,
                                                    const float* __restrict__ att,
                                                    const int* __restrict__ midx,
                                                    const int* __restrict__ mmask) {
    extern __shared__ char sm[];
    int tid = threadIdx.x;
    int lane = tid & 31, warp = tid >> 5;

    if (blockIdx.x >= 128) {
        // ---------- transpose path ----------
        int tb = blockIdx.x - 128;           // 0..383
        if (tb == 0) {
            for (int i = tid; i < ST; i += 1024) {
                int s = i / NEE, tt = i % NEE;
                if (s <= tt) {
                    int r = s*NEE - s*(s+1)/2 + tt;
                    g_ps[r] = s; g_pt[r] = tt;
                }
            }
        }
        int b = tb / 96, rem = tb % 96;
        int l0 = (rem & 15) * 64, d0 = (rem >> 4) * 128;
        float (*ts)[129] = (float(*)[129])sm;   // 64 x 129 floats = 33 KB

#pragma unroll
        for (int p = 0; p < 8; p++) {
            int l = (tid >> 7) + p*8;            // 0..63
            int d = tid & 127;
            ts[l][d] = seq[((size_t)b*LL + l0 + l)*DD + d0 + d];
        }
        __syncthreads();
#pragma unroll
        for (int q = 0; q < 4; q++) {
            int d = warp + q*32;                 // 0..127
            __half2 v = __floats2half2_rn(ts[2*lane][d], ts[2*lane+1][d]);
            *(__half2*)(&g_BT[((size_t)b*DD + d0 + d)*LL + l0 + 2*lane]) = v;
        }
        // publish
        __threadfence();
        __syncthreads();
        if (tid == 0) atomicAdd(&g_cnt[b], 1);
        return;
    }

    // ---------- fuse path ----------
    float* As = (float*)sm;                 // [h*NEE+e][32] = 64512 B
    __shared__ int   sidx[NEE*MM];
    __shared__ int   scnt[NEE];
    __shared__ float sinv[NEE];

    int fb = blockIdx.x;                    // 0..127
    int b = fb >> 5, j = fb & 31, l0 = j * 32;

    if (tid < NEE) {
        int e = tid, k = 0;
        const int* ip = midx  + (b*NEE + e)*MM;
        const int* mp = mmask + (b*NEE + e)*MM;
#pragma unroll
        for (int m = 0; m < MM; m++) {
            int i = ip[m] + 1;
            if (mp[m] > 0 && i < LL) sidx[e*MM + (k++)] = i;
        }
        scnt[e] = k;
        sinv[e] = 1.0f / (float)(k > 0 ? k : 1);
        for (int m = k; m < MM; m++) sidx[e*MM + m] = 0;   // pad -> L2-hot row 0
    }
    __syncthreads();

    // gather: one warp per (h,e); fixed-8 unrolled predicated loads (MLP=8)
    const float* ab0 = att + (size_t)b * HH * LL * LL + l0 + lane;
    for (int he = warp; he < HH*NEE; he += 32) {
        int h = he / NEE, e = he % NEE;
        const float* ab = ab0 + (size_t)h * LL * LL;
        int c = scnt[e];
        float s = 0.0f;
#pragma unroll
        for (int m = 0; m < MM; m++) {
            float v = ab[(size_t)sidx[e*MM + m] * LL];
            s += (m < c) ? v : 0.0f;
        }
        As[he*32 + lane] = s * sinv[e];
    }
    __syncthreads();

    // Gram: lane = l, warp covers t = s+warp (+32)
    const float invH = 1.0f / (float)HH;
    float* zp = g_Zp + (b*32 + j)*PACK;
    for (int s = 0; s < NEE; s++) {
        int t1 = s + warp;
        if (t1 < NEE) {
            float as[HH];
#pragma unroll
            for (int h = 0; h < HH; h++)
                as[h] = As[(h*NEE + s)*32 + lane];
            int rbase = s*NEE - s*(s+1)/2;
            {
                float acc = 0.0f;
#pragma unroll
                for (int h = 0; h < HH; h++)
                    acc = fmaf(as[h], As[(h*NEE + t1)*32 + lane], acc);
                float w = acc * invH;
                g_Wh[((size_t)b*PACK + rbase + t1)*LL + l0 + lane] = __float2half(w);
                float zs = w;
#pragma unroll
                for (int off = 16; off > 0; off >>= 1)
                    zs += __shfl_xor_sync(0xffffffffu, zs, off);
                if (lane == 0) zp[rbase + t1] = zs;
            }
            int t2 = t1 + 32;
            if (t2 < NEE) {
                float acc = 0.0f;
#pragma unroll
                for (int h = 0; h < HH; h++)
                    acc = fmaf(as[h], As[(h*NEE + t2)*32 + lane], acc);
                float w = acc * invH;
                g_Wh[((size_t)b*PACK + rbase + t2)*LL + l0 + lane] = __float2half(w);
                float zs = w;
#pragma unroll
                for (int off = 16; off > 0; off >>= 1)
                    zs += __shfl_xor_sync(0xffffffffu, zs, off);
                if (lane == 0) zp[rbase + t2] = zs;
            }
        }
    }
    // publish
    __threadfence();
    __syncthreads();
    if (tid == 0) atomicAdd(&g_cnt[b], 1);
}

// ---------------- Kernel C: fp16 HMMA GEMM, flag-gated ----------------
#define GBM 128
#define GBN 96
#define NST 4
#define OFF_A 0
#define OFF_B 16384
#define STAGEB 28672               // A 16KB + B 12KB
#define NKS 16                     // 1024 / 64

__global__ void __launch_bounds__(256, 2) mma_gemm(float* __restrict__ out) {
    extern __shared__ __align__(1024) char smc[];
    uint32_t sbase = smem_u32(smc);

    int tid = threadIdx.x, lane = tid & 31, wid = tid >> 5;
    int wm = wid & 3, wn = wid >> 2;          // 4 x 2 warp grid (warp tile 32x48)
    int b  = blockIdx.z;
    int m0 = blockIdx.y * GBM;
    int n0 = blockIdx.x * GBN;

    // gate on prep completion for this batch (and batch 0 for g_ps/g_pt)
    if (tid == 0) {
        while (atomicAdd(&g_cnt[b], 0) < 128 || atomicAdd(&g_cnt[0], 0) < 128)
            __nanosleep(200);
        __threadfence();
    }
    __syncthreads();

    const char* gA = (const char*)(g_Wh + ((size_t)b*PACK + m0)*LL);
    const char* gB = (const char*)(g_BT + ((size_t)b*DD   + n0)*LL);

    auto load_stage = [&](int ks) {
        uint32_t sdst = sbase + (uint32_t)(ks % NST) * STAGEB;
        size_t kbyte = (size_t)ks * 128;       // 64 fp16
#pragma unroll
        for (int i = 0; i < 4; i++) {          // A: 128 rows x 8 chunks
            int idx = tid + i*256;             // 0..1023
            int row = idx >> 3, c = idx & 7;
            const char* src = gA + (size_t)row*2048 + kbyte + c*16;
            uint32_t so = (uint32_t)(row*128 + ((c ^ (row & 7)) << 4));
            cp16(sdst + OFF_A + so, src);
        }
#pragma unroll
        for (int i = 0; i < 3; i++) {          // B: 96 rows x 8 chunks
            int idx = tid + i*256;             // 0..767
            int row = idx >> 3, c = idx & 7;
            const char* src = gB + (size_t)row*2048 + kbyte + c*16;
            uint32_t so = (uint32_t)(row*128 + ((c ^ (row & 7)) << 4));
            cp16(sdst + OFF_B + so, src);
        }
    };

    load_stage(0); CP_COMMIT();
    load_stage(1); CP_COMMIT();
    load_stage(2); CP_COMMIT();

    // Z reduction overlapped with pipeline warm-up
    float zsc[2][2];
#pragma unroll
    for (int mi = 0; mi < 2; mi++)
#pragma unroll
        for (int h = 0; h < 2; h++) {
            int r = m0 + wm*32 + mi*16 + h*8 + (lane >> 2);
            const float* zp = g_Zp + b*32*PACK + (lane & 3)*8*PACK + r;
            float z = 0.0f;
#pragma unroll
            for (int q = 0; q < 8; q++) z += zp[q*PACK];
            z += __shfl_xor_sync(0xffffffffu, z, 1);
            z += __shfl_xor_sync(0xffffffffu, z, 2);
            zsc[mi][h] = 1.0f / (z + 1e-5f);
        }

    float acc[2][6][4];
#pragma unroll
    for (int i = 0; i < 2; i++)
#pragma unroll
        for (int j = 0; j < 6; j++)
#pragma unroll
            for (int k = 0; k < 4; k++) acc[i][j][k] = 0.0f;

    // fragment double buffers
    uint32_t ah[2][2][4], bh[2][6][2];

    auto load_frags = [&](uint32_t s0, int kk, int buf) {
#pragma unroll
        for (int mi = 0; mi < 2; mi++) {
            int row = wm*32 + mi*16 + (lane & 15);
            int c = kk*2 + (lane >> 4);
            uint32_t so = (uint32_t)(row*128 + ((c ^ (row & 7)) << 4));
            ldsm4(ah[buf][mi][0], ah[buf][mi][1], ah[buf][mi][2], ah[buf][mi][3],
                  s0 + OFF_A + so);
        }
#pragma unroll
        for (int nj = 0; nj < 3; nj++) {
            int row = wn*48 + nj*16 + (lane & 15);
            int c = kk*2 + (lane >> 4);
            uint32_t so = (uint32_t)(row*128 + ((c ^ (row & 7)) << 4));
            uint32_t r0, r1, r2, r3;
            ldsm4(r0, r1, r2, r3, s0 + OFF_B + so);
            bh[buf][2*nj][0] = r0;   bh[buf][2*nj][1] = r2;
            bh[buf][2*nj+1][0] = r1; bh[buf][2*nj+1][1] = r3;
        }
    };

    for (int ks = 0; ks < NKS; ks++) {
        if (ks < NKS - 3) CP_WAIT2(); else CP_WAIT0();
        __syncthreads();
        if (ks + 3 < NKS) { load_stage(ks + 3); CP_COMMIT(); }

        uint32_t s0 = sbase + (uint32_t)(ks % NST) * STAGEB;
        load_frags(s0, 0, 0);
#pragma unroll
        for (int kk = 0; kk < 4; kk++) {
            int cur = kk & 1;
            if (kk < 3) load_frags(s0, kk + 1, cur ^ 1);
#pragma unroll
            for (int mi = 0; mi < 2; mi++)
#pragma unroll
                for (int ni = 0; ni < 6; ni++)
                    mma16816(acc[mi][ni], ah[cur][mi], bh[cur][ni]);
        }
    }

    // epilogue: scale by precomputed 1/(Z+1e-5), mirror-write (s,t) and (t,s)
#pragma unroll
    for (int mi = 0; mi < 2; mi++) {
#pragma unroll
        for (int h = 0; h < 2; h++) {
            int r = m0 + wm*32 + mi*16 + h*8 + (lane >> 2);
            if (r < NPAIR) {
                int s = g_ps[r], t = g_pt[r];
                float scale = zsc[mi][h];
                float* o1 = out + ((size_t)b*ST + s*NEE + t)*DD;
                float* o2 = out + ((size_t)b*ST + t*NEE + s)*DD;
#pragma unroll
                for (int ni = 0; ni < 6; ni++) {
                    int col = n0 + wn*48 + ni*8 + (lane & 3)*2;
                    float2 v;
                    v.x = acc[mi][ni][h*2+0] * scale;
                    v.y = acc[mi][ni][h*2+1] * scale;
                    *(float2*)(o1 + col) = v;
                    *(float2*)(o2 + col) = v;
                }
            }
        }
    }
}

// ---------------- launch: overlapped prep (high-pri stream) + gated GEMM ----------------
extern "C" void kernel_launch(void* const* d_in, const int* in_sizes, int n_in,
                              void* d_out, int out_size) {
    const float* seq   = (const float*)d_in[0];   // [4,1024,768]
    const float* att   = (const float*)d_in[1];   // [4,12,1024,1024]
    const int*   midx  = (const int*)  d_in[2];   // [4,42,8]
    const int*   mmask = (const int*)  d_in[3];   // [4,42,8]
    float*       out   = (float*)d_out;           // [4,42,42,768]

    static cudaStream_t sp = nullptr;
    static cudaEvent_t  eF = nullptr, eP = nullptr;
    if (!sp) {
        int lo, hi;
        cudaDeviceGetStreamPriorityRange(&lo, &hi);   // hi = greatest priority
        cudaStreamCreateWithPriority(&sp, cudaStreamNonBlocking, hi);
        cudaEventCreateWithFlags(&eF, cudaEventDisableTiming);
        cudaEventCreateWithFlags(&eP, cudaEventDisableTiming);
        cudaFuncSetAttribute(prep_kernel, cudaFuncAttributeMaxDynamicSharedMemorySize, 64512);
        cudaFuncSetAttribute(mma_gemm, cudaFuncAttributeMaxDynamicSharedMemorySize, NST*STAGEB);
    }

    reset_flags<<<1, 32>>>();                         // default stream

    cudaEventRecord(eF, 0);
    cudaStreamWaitEvent(sp, eF, 0);
    prep_kernel<<<512, 1024, 64512, sp>>>(seq, att, midx, mmask);   // high priority
    cudaEventRecord(eP, sp);

    mma_gemm<<<dim3(DD/GBN, PACK/GBM, BB), 256, NST*STAGEB>>>(out); // default, flag-gated

    cudaStreamWaitEvent(0, eP, 0);                    // join prep into capture stream
}

// round 15
// speedup vs baseline: 1.3869x; 1.3869x over previous
#include <cuda_runtime.h>
#include <cuda_fp16.h>
#include <cstdint>

// ---------------- problem constants ----------------
#define BB 4
#define LL 1024
#define DD 768
#define HH 12
#define NEE 42
#define MM 8
#define ST (NEE*NEE)     // 1764
#define NPAIR 903        // pairs with s<=t
#define PACK 1024        // padded packed rows (8 x 128)

// ---------------- device scratch ----------------
__device__ __half g_Wh[(size_t)BB*PACK*LL];   // packed symmetric W (fp16)
__device__ __half g_BT[(size_t)BB*DD*LL];     // seq^T (fp16) [b][d][l]
__device__ float  g_Zp[BB*32*PACK];           // per-ltile partial row sums
__device__ int    g_ps[PACK];                 // packed row -> s
__device__ int    g_pt[PACK];                 // packed row -> t

// ---------------- PTX helpers ----------------
__device__ __forceinline__ uint32_t smem_u32(const void* p) {
    uint32_t a;
    asm("{ .reg .u64 t; cvta.to.shared.u64 t, %1; cvt.u32.u64 %0, t; }" : "=r"(a) : "l"(p));
    return a;
}
__device__ __forceinline__ void cp16(uint32_t dst, const void* src) {
    asm volatile("cp.async.cg.shared.global [%0], [%1], 16;" :: "r"(dst), "l"(src));
}
#define CP_COMMIT() asm volatile("cp.async.commit_group;" ::: "memory")
#define CP_WAIT2()  asm volatile("cp.async.wait_group 2;" ::: "memory")
#define CP_WAIT0()  asm volatile("cp.async.wait_group 0;" ::: "memory")

__device__ __forceinline__ void ldsm4(uint32_t& r0, uint32_t& r1, uint32_t& r2, uint32_t& r3,
                                      uint32_t addr) {
    asm volatile("ldmatrix.sync.aligned.m8n8.x4.shared.b16 {%0,%1,%2,%3}, [%4];"
                 : "=r"(r0), "=r"(r1), "=r"(r2), "=r"(r3) : "r"(addr));
}
__device__ __forceinline__ void mma16816(float* d, const uint32_t* a, const uint32_t* b) {
    asm volatile(
        "mma.sync.aligned.m16n8k16.row.col.f32.f16.f16.f32 "
        "{%0,%1,%2,%3},{%4,%5,%6,%7},{%8,%9},{%0,%1,%2,%3};"
        : "+f"(d[0]), "+f"(d[1]), "+f"(d[2]), "+f"(d[3])
        : "r"(a[0]), "r"(a[1]), "r"(a[2]), "r"(a[3]), "r"(b[0]), "r"(b[1]));
}

// ---------------- Kernel P: merged prep ----------------
// blocks 0..127   : fused ent_att + Gram (s-ownership) + fp16 W + Z partials
// blocks 128..255 : seq transpose+convert -> g_BT (3 tiles each)
// 1024 threads, dyn smem 64512 B; 256 blocks = ONE wave at 2 blocks/SM
__global__ void __launch_bounds__(1024) prep_kernel(const float* __restrict__ seq,
                                                    const float* __restrict__ att,
                                                    const int* __restrict__ midx,
                                                    const int* __restrict__ mmask) {
    extern __shared__ char sm[];
    int tid = threadIdx.x;
    int lane = tid & 31, warp = tid >> 5;

    if (blockIdx.x >= 128) {
        // ---------- transpose path: 3 tiles of (64 l x 128 d) ----------
        int tb = blockIdx.x - 128;           // 0..127
        if (tb == 0) {
            for (int i = tid; i < ST; i += 1024) {
                int s = i / NEE, tt = i % NEE;
                if (s <= tt) {
                    int r = s*NEE - s*(s+1)/2 + tt;
                    g_ps[r] = s; g_pt[r] = tt;
                }
            }
        }
        int b = tb >> 5, q = tb & 31;        // q*3 .. q*3+2 of 96 tiles
        float (*ts)[129] = (float(*)[129])sm;   // 64 x 129 floats = 33 KB

        for (int i = 0; i < 3; i++) {
            int ti = q*3 + i;
            int l0 = (ti & 15) * 64, d0 = (ti >> 4) * 128;
#pragma unroll
            for (int p = 0; p < 8; p++) {
                int l = (tid >> 7) + p*8;        // 0..63
                int d = tid & 127;
                ts[l][d] = seq[((size_t)b*LL + l0 + l)*DD + d0 + d];
            }
            __syncthreads();
#pragma unroll
            for (int qq = 0; qq < 4; qq++) {
                int d = warp + qq*32;            // 0..127
                __half2 v = __floats2half2_rn(ts[2*lane][d], ts[2*lane+1][d]);
                *(__half2*)(&g_BT[((size_t)b*DD + d0 + d)*LL + l0 + 2*lane]) = v;
            }
            __syncthreads();
        }
        return;
    }

    // ---------- fuse path ----------
    float* As = (float*)sm;                 // [h*NEE+e][32] = 64512 B
    __shared__ int   sidx[NEE*MM];
    __shared__ int   scnt[NEE];
    __shared__ float sinv[NEE];

    int fb = blockIdx.x;                    // 0..127
    int b = fb >> 5, j = fb & 31, l0 = j * 32;

    if (tid < NEE) {
        int e = tid, k = 0;
        const int* ip = midx  + (b*NEE + e)*MM;
        const int* mp = mmask + (b*NEE + e)*MM;
#pragma unroll
        for (int m = 0; m < MM; m++) {
            int i = ip[m] + 1;
            if (mp[m] > 0 && i < LL) sidx[e*MM + (k++)] = i;
        }
        scnt[e] = k;
        sinv[e] = 1.0f / (float)(k > 0 ? k : 1);
        for (int m = k; m < MM; m++) sidx[e*MM + m] = 0;   // pad -> L2-hot row 0
    }
    __syncthreads();

    // gather: one warp per (h,e); fixed-8 unrolled predicated loads (MLP=8)  [R8 exact]
    const float* ab0 = att + (size_t)b * HH * LL * LL + l0 + lane;
    for (int he = warp; he < HH*NEE; he += 32) {
        int h = he / NEE, e = he % NEE;
        const float* ab = ab0 + (size_t)h * LL * LL;
        int c = scnt[e];
        float s = 0.0f;
#pragma unroll
        for (int m = 0; m < MM; m++) {
            float v = ab[(size_t)sidx[e*MM + m] * LL];
            s += (m < c) ? v : 0.0f;
        }
        As[he*32 + lane] = s * sinv[e];
    }
    __syncthreads();

    // Gram: s-ownership — warp w owns s = w, w+32; as[] loaded once per s
    const float invH = 1.0f / (float)HH;
    float* zp = g_Zp + (b*32 + j)*PACK;
    for (int si = warp; si < NEE; si += 32) {
        float as[HH];
#pragma unroll
        for (int h = 0; h < HH; h++)
            as[h] = As[(h*NEE + si)*32 + lane];
        int rbase = si*NEE - si*(si+1)/2;
        for (int t = si; t < NEE; t++) {
            float acc = 0.0f;
#pragma unroll
            for (int h = 0; h < HH; h++)
                acc = fmaf(as[h], As[(h*NEE + t)*32 + lane], acc);
            float w = acc * invH;
            g_Wh[((size_t)b*PACK + rbase + t)*LL + l0 + lane] = __float2half(w);
            float zs = w;
#pragma unroll
            for (int off = 16; off > 0; off >>= 1)
                zs += __shfl_xor_sync(0xffffffffu, zs, off);
            if (lane == 0) zp[rbase + t] = zs;
        }
    }
}

// ---------------- Kernel C: fp16 HMMA GEMM [R13 exact] ----------------
#define GBM 128
#define GBN 96
#define NST 4
#define OFF_A 0
#define OFF_B 16384
#define STAGEB 28672               // A 16KB + B 12KB
#define NKS 16                     // 1024 / 64

__global__ void __launch_bounds__(256, 2) mma_gemm(float* __restrict__ out) {
    extern __shared__ __align__(1024) char smc[];
    uint32_t sbase = smem_u32(smc);

    int tid = threadIdx.x, lane = tid & 31, wid = tid >> 5;
    int wm = wid & 3, wn = wid >> 2;          // 4 x 2 warp grid (warp tile 32x48)
    int b  = blockIdx.z;
    int m0 = blockIdx.y * GBM;
    int n0 = blockIdx.x * GBN;

    const char* gA = (const char*)(g_Wh + ((size_t)b*PACK + m0)*LL);
    const char* gB = (const char*)(g_BT + ((size_t)b*DD   + n0)*LL);

    auto load_stage = [&](int ks) {
        uint32_t sdst = sbase + (uint32_t)(ks % NST) * STAGEB;
        size_t kbyte = (size_t)ks * 128;       // 64 fp16
#pragma unroll
        for (int i = 0; i < 4; i++) {          // A: 128 rows x 8 chunks
            int idx = tid + i*256;             // 0..1023
            int row = idx >> 3, c = idx & 7;
            const char* src = gA + (size_t)row*2048 + kbyte + c*16;
            uint32_t so = (uint32_t)(row*128 + ((c ^ (row & 7)) << 4));
            cp16(sdst + OFF_A + so, src);
        }
#pragma unroll
        for (int i = 0; i < 3; i++) {          // B: 96 rows x 8 chunks
            int idx = tid + i*256;             // 0..767
            int row = idx >> 3, c = idx & 7;
            const char* src = gB + (size_t)row*2048 + kbyte + c*16;
            uint32_t so = (uint32_t)(row*128 + ((c ^ (row & 7)) << 4));
            cp16(sdst + OFF_B + so, src);
        }
    };

    load_stage(0); CP_COMMIT();
    load_stage(1); CP_COMMIT();
    load_stage(2); CP_COMMIT();

    // Z reduction overlapped with pipeline warm-up
    float zsc[2][2];
#pragma unroll
    for (int mi = 0; mi < 2; mi++)
#pragma unroll
        for (int h = 0; h < 2; h++) {
            int r = m0 + wm*32 + mi*16 + h*8 + (lane >> 2);
            const float* zp = g_Zp + b*32*PACK + (lane & 3)*8*PACK + r;
            float z = 0.0f;
#pragma unroll
            for (int q = 0; q < 8; q++) z += zp[q*PACK];
            z += __shfl_xor_sync(0xffffffffu, z, 1);
            z += __shfl_xor_sync(0xffffffffu, z, 2);
            zsc[mi][h] = 1.0f / (z + 1e-5f);
        }

    float acc[2][6][4];
#pragma unroll
    for (int i = 0; i < 2; i++)
#pragma unroll
        for (int j = 0; j < 6; j++)
#pragma unroll
            for (int k = 0; k < 4; k++) acc[i][j][k] = 0.0f;

    // fragment double buffers
    uint32_t ah[2][2][4], bh[2][6][2];

    auto load_frags = [&](uint32_t s0, int kk, int buf) {
#pragma unroll
        for (int mi = 0; mi < 2; mi++) {
            int row = wm*32 + mi*16 + (lane & 15);
            int c = kk*2 + (lane >> 4);
            uint32_t so = (uint32_t)(row*128 + ((c ^ (row & 7)) << 4));
            ldsm4(ah[buf][mi][0], ah[buf][mi][1], ah[buf][mi][2], ah[buf][mi][3],
                  s0 + OFF_A + so);
        }
#pragma unroll
        for (int nj = 0; nj < 3; nj++) {
            int row = wn*48 + nj*16 + (lane & 15);
            int c = kk*2 + (lane >> 4);
            uint32_t so = (uint32_t)(row*128 + ((c ^ (row & 7)) << 4));
            uint32_t r0, r1, r2, r3;
            ldsm4(r0, r1, r2, r3, s0 + OFF_B + so);
            bh[buf][2*nj][0] = r0;   bh[buf][2*nj][1] = r2;
            bh[buf][2*nj+1][0] = r1; bh[buf][2*nj+1][1] = r3;
        }
    };

    for (int ks = 0; ks < NKS; ks++) {
        if (ks < NKS - 3) CP_WAIT2(); else CP_WAIT0();
        __syncthreads();
        if (ks + 3 < NKS) { load_stage(ks + 3); CP_COMMIT(); }

        uint32_t s0 = sbase + (uint32_t)(ks % NST) * STAGEB;
        load_frags(s0, 0, 0);
#pragma unroll
        for (int kk = 0; kk < 4; kk++) {
            int cur = kk & 1;
            if (kk < 3) load_frags(s0, kk + 1, cur ^ 1);
#pragma unroll
            for (int mi = 0; mi < 2; mi++)
#pragma unroll
                for (int ni = 0; ni < 6; ni++)
                    mma16816(acc[mi][ni], ah[cur][mi], bh[cur][ni]);
        }
    }

    // epilogue: scale by precomputed 1/(Z+1e-5), mirror-write (s,t) and (t,s)
#pragma unroll
    for (int mi = 0; mi < 2; mi++) {
#pragma unroll
        for (int h = 0; h < 2; h++) {
            int r = m0 + wm*32 + mi*16 + h*8 + (lane >> 2);
            if (r < NPAIR) {
                int s = g_ps[r], t = g_pt[r];
                float scale = zsc[mi][h];
                float* o1 = out + ((size_t)b*ST + s*NEE + t)*DD;
                float* o2 = out + ((size_t)b*ST + t*NEE + s)*DD;
#pragma unroll
                for (int ni = 0; ni < 6; ni++) {
                    int col = n0 + wn*48 + ni*8 + (lane & 3)*2;
                    float2 v;
                    v.x = acc[mi][ni][h*2+0] * scale;
                    v.y = acc[mi][ni][h*2+1] * scale;
                    *(float2*)(o1 + col) = v;
                    *(float2*)(o2 + col) = v;
                }
            }
        }
    }
}

// ---------------- launch ----------------
extern "C" void kernel_launch(void* const* d_in, const int* in_sizes, int n_in,
                              void* d_out, int out_size) {
    const float* seq   = (const float*)d_in[0];   // [4,1024,768]
    const float* att   = (const float*)d_in[1];   // [4,12,1024,1024]
    const int*   midx  = (const int*)  d_in[2];   // [4,42,8]
    const int*   mmask = (const int*)  d_in[3];   // [4,42,8]
    float*       out   = (float*)d_out;           // [4,42,42,768]

    cudaFuncSetAttribute(prep_kernel, cudaFuncAttributeMaxDynamicSharedMemorySize, 64512);
    cudaFuncSetAttribute(mma_gemm, cudaFuncAttributeMaxDynamicSharedMemorySize, NST*STAGEB);

    prep_kernel<<<256, 1024, 64512>>>(seq, att, midx, mmask);
    mma_gemm<<<dim3(DD/GBN, PACK/GBM, BB), 256, NST*STAGEB>>>(out);
}